// round 3
// baseline (speedup 1.0000x reference)
#include <cuda_runtime.h>
#include <cstdint>

#define NN 50000
#define NE 1600000

typedef unsigned long long u64;

// ---------------- device scratch (no allocs allowed) ----------------
__device__ int g_is64;
__device__ int g_src[NE];
__device__ int g_dst[NE];
__device__ __align__(16) float g_hn [NN * 32];   // per-node projected features (current layer)
__device__ __align__(16) float g_Ls [NN * 4];    // <hn, a_s> per head
__device__ __align__(16) float g_Ld [NN * 4];    // <hn, a_d> per head
__device__ __align__(16) float g_P1 [NN * 32];   // hn @ Weo[0:32]   (layer 1 only)
__device__ __align__(16) float g_P2 [NN * 32];   // hn @ Weo[32:64]  (layer 1 only)
__device__ __align__(16) float g_num[NN * 32];   // softmax-weighted message numerator
__device__ __align__(16) float g_den[NN * 4];    // softmax denominator per head
__device__ __align__(16) float g_x1 [NN * 32];   // layer-1 node output
__device__ __align__(16) float g_y1 [(size_t)NE * 32]; // layer-1 edge output (layer-2 edge feats)

// ---------------- f32x2 packed-math helpers (sm_103a) ----------------
__device__ __forceinline__ u64 pk2(float a) {            // {a, a}
    u64 r; asm("mov.b64 %0, {%1, %1};" : "=l"(r) : "f"(a)); return r;
}
__device__ __forceinline__ void upk(u64 v, float& a, float& b) {
    asm("mov.b64 {%0, %1}, %2;" : "=f"(a), "=f"(b) : "l"(v));
}
__device__ __forceinline__ void fma2(u64& d, u64 a, u64 b) {   // d += a*b (2x fp32)
    asm("fma.rn.f32x2 %0, %1, %2, %0;" : "+l"(d) : "l"(a), "l"(b));
}
__device__ __forceinline__ u64 add2(u64 a, u64 b) {
    u64 r; asm("add.rn.f32x2 %0, %1, %2;" : "=l"(r) : "l"(a), "l"(b)); return r;
}
__device__ __forceinline__ u64 mul2(u64 a, u64 b) {
    u64 r; asm("mul.rn.f32x2 %0, %1, %2;" : "=l"(r) : "l"(a), "l"(b)); return r;
}

// 16-byte vector reduction into global (L2-side atomic, no return)
__device__ __forceinline__ void red4(float* p, float a, float b, float c, float d) {
    asm volatile("red.global.add.v4.f32 [%0], {%1, %2, %3, %4};"
                 :: "l"(p), "f"(a), "f"(b), "f"(c), "f"(d) : "memory");
}

// ---------------- index dtype detection ----------------
// If edge_indexes is int64, every value < 50000 => every odd 32-bit word is 0.
// If int32, odd words are random node ids (P[all 64 zero] ~ 0).
__global__ void k_detect(const int* __restrict__ raw) {
    if (threadIdx.x == 0 && blockIdx.x == 0) {
        int s = 0;
#pragma unroll
        for (int i = 0; i < 64; i++) s |= raw[2 * i + 1];
        g_is64 = (s == 0) ? 1 : 0;
    }
}

// Index normalization + accumulator zeroing fused (same 1.6M-thread grid).
__global__ void k_conv(const void* __restrict__ raw) {
    int e = blockIdx.x * blockDim.x + threadIdx.x;
    if (e >= NE) return;
    if (g_is64) {
        const long long* p = (const long long*)raw;
        g_src[e] = (int)p[e];
        g_dst[e] = (int)p[NE + e];
    } else {
        const int* p = (const int*)raw;
        g_src[e] = p[e];
        g_dst[e] = p[NE + e];
    }
    // NN*32 == NE: thread e zeros accumulator word e
    g_num[e] = 0.f;
    if (e < NN * 4) g_den[e] = 0.f;
}

// ---------------- node-side precompute ----------------
// One warp per node. lane j owns output channel j (j = h*8+d).
template <int K, bool DOP, bool FROMX1>
__global__ void k_node_prep(const float* __restrict__ X,
                            const float* __restrict__ Wn, const float* __restrict__ bn,
                            const float* __restrict__ as_, const float* __restrict__ ad_,
                            const float* __restrict__ Weo) {
    int gw   = (blockIdx.x * blockDim.x + threadIdx.x) >> 5;
    int lane = threadIdx.x & 31;
    if (gw >= NN) return;
    const float* x = (FROMX1 ? (const float*)g_x1 : X) + (size_t)gw * K;
    float acc = bn[lane];
#pragma unroll 8
    for (int k = 0; k < K; k++)
        acc = fmaf(__ldg(x + k), Wn[k * 32 + lane], acc);
    g_hn[gw * 32 + lane] = acc;

    float ts = acc * as_[lane];
    float td = acc * ad_[lane];
#pragma unroll
    for (int off = 1; off < 8; off <<= 1) {
        ts += __shfl_xor_sync(0xffffffffu, ts, off);
        td += __shfl_xor_sync(0xffffffffu, td, off);
    }
    if ((lane & 7) == 0) {
        g_Ls[gw * 4 + (lane >> 3)] = ts;
        g_Ld[gw * 4 + (lane >> 3)] = td;
    }
    if (DOP) {
        __shared__ float sh[8][32];
        int w = threadIdx.x >> 5;
        sh[w][lane] = acc;
        __syncwarp();
        float p1 = 0.f, p2 = 0.f;
#pragma unroll 8
        for (int k = 0; k < 32; k++) {
            float v = sh[w][k];
            p1 = fmaf(v, Weo[k * 32 + lane],        p1);
            p2 = fmaf(v, Weo[(32 + k) * 32 + lane], p2);
        }
        g_P1[gw * 32 + lane] = p1;
        g_P2[gw * 32 + lane] = p2;
    }
}

// ---------------- layer-1 edge kernel ----------------
// One thread per edge. Weights in shared (broadcast LDS.128), math in f32x2 pairs.
__global__ __launch_bounds__(256) void k_edge1(
        const float* __restrict__ EF,
        const float* __restrict__ We, const float* __restrict__ be,
        const float* __restrict__ ae, const float* __restrict__ Weo,
        const float* __restrict__ beo) {
    __shared__ __align__(16) float sWe[1024], sW3[1024];
    __shared__ __align__(16) float sAe[32], sBe[32], sBeo[32];
    for (int i = threadIdx.x; i < 1024; i += 256) {
        sWe[i] = We[i];
        sW3[i] = Weo[64 * 32 + i];     // third row-block of Weo
    }
    if (threadIdx.x < 32) {
        sAe[threadIdx.x]  = ae[threadIdx.x];
        sBe[threadIdx.x]  = be[threadIdx.x];
        sBeo[threadIdx.x] = beo[threadIdx.x];
    }
    __syncthreads();

    int e = blockIdx.x * 256 + threadIdx.x;
    if (e >= NE) return;
    int src = g_src[e], dst = g_dst[e];

    // edge features -> registers
    float ef[32];
    const float4* efp = (const float4*)(EF + (size_t)e * 32);
#pragma unroll
    for (int i = 0; i < 8; i++) {
        float4 v = __ldg(efp + i);
        ef[4 * i] = v.x; ef[4 * i + 1] = v.y; ef[4 * i + 2] = v.z; ef[4 * i + 3] = v.w;
    }

    // he = ef @ We + be, channels packed in pairs
    u64 hep[16];
    const u64* be2 = (const u64*)sBe;
#pragma unroll
    for (int j = 0; j < 16; j++) hep[j] = be2[j];
    const ulonglong2* W2 = (const ulonglong2*)sWe;
#pragma unroll
    for (int k = 0; k < 32; k++) {
        u64 xx = pk2(ef[k]);
#pragma unroll
        for (int p = 0; p < 8; p++) {
            ulonglong2 w = W2[k * 8 + p];
            fma2(hep[2 * p],     w.x, xx);
            fma2(hep[2 * p + 1], w.y, xx);
        }
    }

    // attention logits per head -> exp (no max subtraction; range-safe in fp32)
    float4 ls4 = __ldg((const float4*)g_Ls + src);
    float4 ld4 = __ldg((const float4*)g_Ld + dst);
    float lsv[4] = {ls4.x, ls4.y, ls4.z, ls4.w};
    float ldv[4] = {ld4.x, ld4.y, ld4.z, ld4.w};
    const u64* ae2 = (const u64*)sAe;
    float ex[4];
#pragma unroll
    for (int h = 0; h < 4; h++) {
        u64 acc = 0ull;                        // {+0.f, +0.f}
#pragma unroll
        for (int p = 0; p < 4; p++) fma2(acc, hep[h * 4 + p], ae2[h * 4 + p]);
        float a, b; upk(acc, a, b);
        float lg = lsv[h] + ldv[h] + a + b;
        lg = lg > 0.f ? lg : 0.2f * lg;        // leaky_relu(0.2)
        ex[h] = __expf(lg);
    }
    red4(&g_den[dst * 4], ex[0], ex[1], ex[2], ex[3]);

    // unnormalized messages: num[dst] += ex_h * (hs + he)
    const ulonglong2* hn4 = (const ulonglong2*)g_hn + src * 8;
#pragma unroll
    for (int i = 0; i < 8; i++) {
        ulonglong2 hs = __ldg(hn4 + i);
        u64 xh = pk2(ex[i >> 1]);
        u64 m0 = mul2(add2(hs.x, hep[2 * i]),     xh);
        u64 m1 = mul2(add2(hs.y, hep[2 * i + 1]), xh);
        float a, b, c, d; upk(m0, a, b); upk(m1, c, d);
        red4(&g_num[dst * 32 + 4 * i], a, b, c, d);
    }

    // edge output: y = softmax( he@W3 + P1[src] + P2[dst] + beo )
    u64 qp[16];
    const u64* beo2 = (const u64*)sBeo;
#pragma unroll
    for (int j = 0; j < 16; j++) qp[j] = beo2[j];
    const ulonglong2* W3 = (const ulonglong2*)sW3;
#pragma unroll
    for (int kp = 0; kp < 16; kp++) {
        float ka, kb; upk(hep[kp], ka, kb);
        u64 xa = pk2(ka), xb = pk2(kb);
#pragma unroll
        for (int p = 0; p < 8; p++) {
            ulonglong2 w = W3[(2 * kp) * 8 + p];
            fma2(qp[2 * p],     w.x, xa);
            fma2(qp[2 * p + 1], w.y, xa);
        }
#pragma unroll
        for (int p = 0; p < 8; p++) {
            ulonglong2 w = W3[(2 * kp + 1) * 8 + p];
            fma2(qp[2 * p],     w.x, xb);
            fma2(qp[2 * p + 1], w.y, xb);
        }
    }
    const ulonglong2* p1p = (const ulonglong2*)g_P1 + src * 8;
    const ulonglong2* p2p = (const ulonglong2*)g_P2 + dst * 8;
#pragma unroll
    for (int i = 0; i < 8; i++) {
        ulonglong2 a = __ldg(p1p + i), b = __ldg(p2p + i);
        qp[2 * i]     = add2(qp[2 * i],     add2(a.x, b.x));
        qp[2 * i + 1] = add2(qp[2 * i + 1], add2(a.y, b.y));
    }
    float q[32];
#pragma unroll
    for (int j = 0; j < 16; j++) upk(qp[j], q[2 * j], q[2 * j + 1]);
    float mx = -1e30f;
#pragma unroll
    for (int j = 0; j < 32; j++) mx = fmaxf(mx, q[j]);
    float s = 0.f;
#pragma unroll
    for (int j = 0; j < 32; j++) { q[j] = __expf(q[j] - mx); s += q[j]; }
    float inv = 1.f / s;
    float4* yp = (float4*)(g_y1 + (size_t)e * 32);
#pragma unroll
    for (int i = 0; i < 8; i++)
        yp[i] = make_float4(q[4 * i] * inv, q[4 * i + 1] * inv,
                            q[4 * i + 2] * inv, q[4 * i + 3] * inv);
}

// ---------------- layer-2 edge kernel ----------------
// Layer-2 edge update (y2) is dead code: final head reads nodes only.
__global__ __launch_bounds__(256) void k_edge2(
        const float* __restrict__ We, const float* __restrict__ be,
        const float* __restrict__ ae) {
    __shared__ __align__(16) float sWe[1024];
    __shared__ __align__(16) float sAe[32], sBe[32];
    for (int i = threadIdx.x; i < 1024; i += 256) sWe[i] = We[i];
    if (threadIdx.x < 32) { sAe[threadIdx.x] = ae[threadIdx.x]; sBe[threadIdx.x] = be[threadIdx.x]; }
    __syncthreads();

    int e = blockIdx.x * 256 + threadIdx.x;
    if (e >= NE) return;
    int src = g_src[e], dst = g_dst[e];

    float ef[32];
    const float4* efp = (const float4*)(g_y1 + (size_t)e * 32);
#pragma unroll
    for (int i = 0; i < 8; i++) {
        float4 v = __ldg(efp + i);
        ef[4 * i] = v.x; ef[4 * i + 1] = v.y; ef[4 * i + 2] = v.z; ef[4 * i + 3] = v.w;
    }

    u64 hep[16];
    const u64* be2 = (const u64*)sBe;
#pragma unroll
    for (int j = 0; j < 16; j++) hep[j] = be2[j];
    const ulonglong2* W2 = (const ulonglong2*)sWe;
#pragma unroll
    for (int k = 0; k < 32; k++) {
        u64 xx = pk2(ef[k]);
#pragma unroll
        for (int p = 0; p < 8; p++) {
            ulonglong2 w = W2[k * 8 + p];
            fma2(hep[2 * p],     w.x, xx);
            fma2(hep[2 * p + 1], w.y, xx);
        }
    }

    float4 ls4 = __ldg((const float4*)g_Ls + src);
    float4 ld4 = __ldg((const float4*)g_Ld + dst);
    float lsv[4] = {ls4.x, ls4.y, ls4.z, ls4.w};
    float ldv[4] = {ld4.x, ld4.y, ld4.z, ld4.w};
    const u64* ae2 = (const u64*)sAe;
    float ex[4];
#pragma unroll
    for (int h = 0; h < 4; h++) {
        u64 acc = 0ull;
#pragma unroll
        for (int p = 0; p < 4; p++) fma2(acc, hep[h * 4 + p], ae2[h * 4 + p]);
        float a, b; upk(acc, a, b);
        float lg = lsv[h] + ldv[h] + a + b;
        lg = lg > 0.f ? lg : 0.2f * lg;
        ex[h] = __expf(lg);
    }
    red4(&g_den[dst * 4], ex[0], ex[1], ex[2], ex[3]);

    const ulonglong2* hn4 = (const ulonglong2*)g_hn + src * 8;
#pragma unroll
    for (int i = 0; i < 8; i++) {
        ulonglong2 hs = __ldg(hn4 + i);
        u64 xh = pk2(ex[i >> 1]);
        u64 m0 = mul2(add2(hs.x, hep[2 * i]),     xh);
        u64 m1 = mul2(add2(hs.y, hep[2 * i + 1]), xh);
        float a, b, c, d; upk(m0, a, b); upk(m1, c, d);
        red4(&g_num[dst * 32 + 4 * i], a, b, c, d);
    }
}

// ---------------- node finalize: layer 1 (divide + softmax), re-zero accumulators ----------------
__global__ void k_fin1() {
    int n = blockIdx.x * blockDim.x + threadIdx.x;
    if (n >= NN) return;
    float4 d4 = *((const float4*)g_den + n);
    *((float4*)g_den + n) = make_float4(0.f, 0.f, 0.f, 0.f);   // reset for layer 2
    float den[4] = {d4.x, d4.y, d4.z, d4.w};
    float4* np = (float4*)g_num + n * 8;
    float v[32];
#pragma unroll
    for (int i = 0; i < 8; i++) {
        float4 a = np[i];
        np[i] = make_float4(0.f, 0.f, 0.f, 0.f);               // reset for layer 2
        float id = 1.f / (den[i >> 1] + 1e-9f);
        v[4 * i] = a.x * id; v[4 * i + 1] = a.y * id;
        v[4 * i + 2] = a.z * id; v[4 * i + 3] = a.w * id;
    }
    float mx = -1e30f;
#pragma unroll
    for (int j = 0; j < 32; j++) mx = fmaxf(mx, v[j]);
    float s = 0.f;
#pragma unroll
    for (int j = 0; j < 32; j++) { v[j] = __expf(v[j] - mx); s += v[j]; }
    float inv = 1.f / s;
    float4* xp = (float4*)g_x1 + n * 8;
#pragma unroll
    for (int i = 0; i < 8; i++)
        xp[i] = make_float4(v[4 * i] * inv, v[4 * i + 1] * inv,
                            v[4 * i + 2] * inv, v[4 * i + 3] * inv);
}

// ---------------- node finalize: layer 2 (divide + relu) + linear head ----------------
__global__ void k_fin2(const float* __restrict__ Wl, const float* __restrict__ bl,
                       float* __restrict__ out) {
    int n = blockIdx.x * blockDim.x + threadIdx.x;
    if (n >= NN) return;
    float4 d4 = *((const float4*)g_den + n);
    float den[4] = {d4.x, d4.y, d4.z, d4.w};
    const float4* np = (const float4*)g_num + n * 8;
    float acc = bl[0];
#pragma unroll
    for (int i = 0; i < 8; i++) {
        float4 a = np[i];
        float id = 1.f / (den[i >> 1] + 1e-9f);
        float x0 = fmaxf(a.x * id, 0.f);
        float x1 = fmaxf(a.y * id, 0.f);
        float x2 = fmaxf(a.z * id, 0.f);
        float x3 = fmaxf(a.w * id, 0.f);
        acc = fmaf(x0, Wl[4 * i],     acc);
        acc = fmaf(x1, Wl[4 * i + 1], acc);
        acc = fmaf(x2, Wl[4 * i + 2], acc);
        acc = fmaf(x3, Wl[4 * i + 3], acc);
    }
    out[n] = acc;
}

// ---------------- launch ----------------
extern "C" void kernel_launch(void* const* d_in, const int* in_sizes, int n_in,
                              void* d_out, int out_size) {
    const float* nodeF = (const float*)d_in[0];
    const float* edgeF = (const float*)d_in[1];
    const void*  eidx  = d_in[2];
    const float *Wn1 = (const float*)d_in[3],  *bn1 = (const float*)d_in[4];
    const float *We1 = (const float*)d_in[5],  *be1 = (const float*)d_in[6];
    const float *as1 = (const float*)d_in[7],  *ad1 = (const float*)d_in[8];
    const float *ae1 = (const float*)d_in[9];
    const float *Weo1 = (const float*)d_in[10], *beo1 = (const float*)d_in[11];
    const float *Wn2 = (const float*)d_in[12], *bn2 = (const float*)d_in[13];
    const float *We2 = (const float*)d_in[14], *be2 = (const float*)d_in[15];
    const float *as2 = (const float*)d_in[16], *ad2 = (const float*)d_in[17];
    const float *ae2 = (const float*)d_in[18];
    // d_in[19] (Weo2) and d_in[20] (beo2) are dead: layer-2 edge output is unused.
    const float *Wl = (const float*)d_in[21], *bl = (const float*)d_in[22];

    const int TB = 256;
    const int gE = (NE + TB - 1) / TB;           // 6250
    const int gW = (NN * 32 + TB - 1) / TB;      // 6250 (warp-per-node kernels)
    const int gN = (NN + TB - 1) / TB;           // 196

    k_detect<<<1, 32>>>((const int*)eidx);
    k_conv<<<gE, TB>>>(eidx);                    // indexes + zero num/den

    // ---- layer 1 ----
    k_node_prep<128, true, false><<<gW, TB>>>(nodeF, Wn1, bn1, as1, ad1, Weo1);
    k_edge1<<<gE, TB>>>(edgeF, We1, be1, ae1, Weo1, beo1);
    k_fin1<<<gN, TB>>>();                        // also re-zeros num/den for layer 2

    // ---- layer 2 ----
    k_node_prep<32, false, true><<<gW, TB>>>(nullptr, Wn2, bn2, as2, ad2, Weo1 /*unused*/);
    k_edge2<<<gE, TB>>>(We2, be2, ae2);
    k_fin2<<<gN, TB>>>(Wl, bl, (float*)d_out);
}